// round 2
// baseline (speedup 1.0000x reference)
#include <cuda_runtime.h>
#include <math.h>
#include <stdint.h>

#define B_  4
#define L_  1024
#define D_  1024
#define H_  16
#define DH_ 64
#define M_  (B_*L_)   /* 4096 rows */

// Scratch (allocation-free rule: __device__ globals)
__device__ float g_q[(size_t)M_ * D_];
__device__ float g_k[(size_t)M_ * D_];
__device__ float g_v[(size_t)M_ * D_];
__device__ float g_attn[(size_t)M_ * D_];

// ---------------------------------------------------------------------------
// SGEMM + bias: C[M_,1024] = A[M_,1024] @ W[1024,1024] + bias[1024]
// 128x64 CTA tile, K-step 16, 256 threads, 8x4 per-thread microtile.
// ---------------------------------------------------------------------------
#define GBM 128
#define GBN 64
#define GBK 16

__global__ __launch_bounds__(256) void sgemm_bias_kernel(
    const float* __restrict__ A, const float* __restrict__ W,
    const float* __restrict__ bias, float* __restrict__ C)
{
    const int N = D_, K = D_;
    __shared__ float As[GBK][GBM + 4];   // stored transposed: As[k][m]
    __shared__ float Bs[GBK][GBN + 4];

    const int m0 = blockIdx.y * GBM;
    const int n0 = blockIdx.x * GBN;
    const int tid = threadIdx.x;
    const int tx = tid & 15;       // -> n
    const int ty = tid >> 4;       // -> m

    float acc[8][4];
#pragma unroll
    for (int i = 0; i < 8; i++)
#pragma unroll
        for (int j = 0; j < 4; j++) acc[i][j] = 0.f;

    for (int k0 = 0; k0 < K; k0 += GBK) {
        // Load A tile: 128x16 floats, 2 float4 per thread, store transposed
#pragma unroll
        for (int f = 0; f < 2; f++) {
            int t4  = tid + f * 256;          // 0..511 float4 index
            int row = t4 >> 2;                // 0..127
            int kk  = (t4 & 3) << 2;          // 0,4,8,12
            float4 v = *(const float4*)(A + (size_t)(m0 + row) * K + k0 + kk);
            As[kk + 0][row] = v.x;
            As[kk + 1][row] = v.y;
            As[kk + 2][row] = v.z;
            As[kk + 3][row] = v.w;
        }
        // Load W tile: 16x64 floats, 1 float4 per thread
        {
            int row = tid >> 4;               // 0..15
            int col = (tid & 15) << 2;        // 0..60
            *(float4*)&Bs[row][col] =
                *(const float4*)(W + (size_t)(k0 + row) * N + n0 + col);
        }
        __syncthreads();

#pragma unroll
        for (int k = 0; k < GBK; k++) {
            float a[8], b[4];
            float4 a0 = *(float4*)&As[k][ty * 8];
            float4 a1 = *(float4*)&As[k][ty * 8 + 4];
            a[0] = a0.x; a[1] = a0.y; a[2] = a0.z; a[3] = a0.w;
            a[4] = a1.x; a[5] = a1.y; a[6] = a1.z; a[7] = a1.w;
            float4 bv = *(float4*)&Bs[k][tx * 4];
            b[0] = bv.x; b[1] = bv.y; b[2] = bv.z; b[3] = bv.w;
#pragma unroll
            for (int i = 0; i < 8; i++)
#pragma unroll
                for (int j = 0; j < 4; j++)
                    acc[i][j] = fmaf(a[i], b[j], acc[i][j]);
        }
        __syncthreads();
    }

#pragma unroll
    for (int i = 0; i < 8; i++) {
        int m = m0 + ty * 8 + i;
#pragma unroll
        for (int j = 0; j < 4; j++) {
            int n = n0 + tx * 4 + j;
            C[(size_t)m * N + n] = acc[i][j] + bias[n];
        }
    }
}

// ---------------------------------------------------------------------------
// Attention: per CTA = (b, h, 32-row i-tile).
//   scores S[32][1024] in smem, softmax-max/Z, top-32 extraction per row,
//   renormalized weights, 32-term weighted V gather.
// ---------------------------------------------------------------------------
#define ITILE 32
#define ATTN_SMEM ((32 * 1024 + 32 * 64 + 64 * 65) * 4)   /* 155,904 B */

__global__ __launch_bounds__(256) void attn_topk_kernel(
    const float* __restrict__ Q, const float* __restrict__ K,
    const float* __restrict__ V, float* __restrict__ Oa)
{
    extern __shared__ float sm[];
    float* sS = sm;                      // 32*1024
    float* sQ = sS + 32 * 1024;          // 32*64
    float* sK = sQ + 32 * 64;            // 64 rows, stride 65 (bank-conflict free)

    const int itile = blockIdx.x;
    const int h     = blockIdx.y;
    const int b     = blockIdx.z;
    const int i0    = itile * ITILE;
    const int tid   = threadIdx.x;
    const int lane  = tid & 31;
    const int w     = tid >> 5;          // warp id 0..7
    const size_t headoff = (size_t)h * DH_;

    // Load Q tile (32x64)
#pragma unroll
    for (int f = 0; f < 2; f++) {
        int e4  = tid + f * 256;         // 0..511
        int row = e4 >> 4;               // 0..31
        int c4  = (e4 & 15) << 2;        // 0..60
        *(float4*)&sQ[row * 64 + c4] =
            *(const float4*)(Q + ((size_t)(b * L_ + i0 + row)) * D_ + headoff + c4);
    }
    __syncthreads();

    // Scores: S = (Q Kt)/8 over 16 chunks of 64 keys
    for (int jc = 0; jc < 16; jc++) {
        int j0 = jc * 64;
#pragma unroll
        for (int f = 0; f < 4; f++) {
            int e4  = tid + f * 256;     // 0..1023
            int row = e4 >> 4;           // 0..63
            int c4  = (e4 & 15) << 2;
            float4 v = *(const float4*)(K + ((size_t)(b * L_ + j0 + row)) * D_ + headoff + c4);
            float* dst = &sK[row * 65 + c4];
            dst[0] = v.x; dst[1] = v.y; dst[2] = v.z; dst[3] = v.w;
        }
        __syncthreads();

        float acc[4][2];
#pragma unroll
        for (int r = 0; r < 4; r++) { acc[r][0] = 0.f; acc[r][1] = 0.f; }
#pragma unroll 4
        for (int k = 0; k < 64; k++) {
            float kv0 = sK[lane * 65 + k];
            float kv1 = sK[(lane + 32) * 65 + k];
#pragma unroll
            for (int r = 0; r < 4; r++) {
                float qv = sQ[(w + 8 * r) * 64 + k];
                acc[r][0] = fmaf(qv, kv0, acc[r][0]);
                acc[r][1] = fmaf(qv, kv1, acc[r][1]);
            }
        }
#pragma unroll
        for (int r = 0; r < 4; r++) {
            sS[(w + 8 * r) * 1024 + j0 + lane]      = acc[r][0] * 0.125f;
            sS[(w + 8 * r) * 1024 + j0 + lane + 32] = acc[r][1] * 0.125f;
        }
        __syncthreads();
    }

    // Per-warp rows {w, w+8, w+16, w+24}: softmax stats, top-32, output
    for (int rr = 0; rr < 4; rr++) {
        int i = w + rr * 8;
        float* row = sS + i * 1024;

        float m = -1e30f;
#pragma unroll
        for (int t = 0; t < 32; t++) m = fmaxf(m, row[lane + 32 * t]);
#pragma unroll
        for (int o = 16; o; o >>= 1) m = fmaxf(m, __shfl_xor_sync(0xffffffffu, m, o));

        float z = 0.f;
#pragma unroll
        for (int t = 0; t < 32; t++) {
            float e = __expf(row[lane + 32 * t] - m);
            row[lane + 32 * t] = e;
            z += e;
        }
#pragma unroll
        for (int o = 16; o; o >>= 1) z += __shfl_xor_sync(0xffffffffu, z, o);

        // lane-local best over its 32-element stripe (j % 32 == lane)
        float bv = -1.f; int bj = 0;
#pragma unroll
        for (int t = 0; t < 32; t++) {
            float vv = row[lane + 32 * t];
            if (vv > bv) { bv = vv; bj = lane + 32 * t; }
        }

        float sumk = 0.f, selw = 0.f; int selj = 0;
        for (int s = 0; s < 32; s++) {
            float v = bv; int j = bj;
#pragma unroll
            for (int o = 16; o; o >>= 1) {
                float v2 = __shfl_xor_sync(0xffffffffu, v, o);
                int   j2 = __shfl_xor_sync(0xffffffffu, j, o);
                if (v2 > v || (v2 == v && j2 < j)) { v = v2; j = j2; }
            }
            sumk += v;
            if (lane == s) { selw = v; selj = j; }
            if ((j & 31) == lane) {           // winning lane: consume + rescan
                row[j] = -1.f;
                bv = -1.f; bj = 0;
#pragma unroll
                for (int t = 0; t < 32; t++) {
                    float vv = row[lane + 32 * t];
                    if (vv > bv) { bv = vv; bj = lane + 32 * t; }
                }
            }
        }

        // w_j = e_j / (sum_top32(e) + 1e-8 * Z_e)  — exact renormalization
        float wgt = selw / (sumk + 1e-8f * z);

        float acc0 = 0.f, acc1 = 0.f;
#pragma unroll
        for (int t = 0; t < 32; t++) {
            int   j  = __shfl_sync(0xffffffffu, selj, t);
            float ww = __shfl_sync(0xffffffffu, wgt,  t);
            const float* vr = V + ((size_t)(b * L_ + j)) * D_ + headoff;
            acc0 = fmaf(ww, vr[lane], acc0);
            acc1 = fmaf(ww, vr[lane + 32], acc1);
        }
        size_t orow = ((size_t)(b * L_ + i0 + i)) * D_ + headoff;
        Oa[orow + lane]      = acc0;
        Oa[orow + lane + 32] = acc1;
    }
}

// ---------------------------------------------------------------------------
extern "C" void kernel_launch(void* const* d_in, const int* in_sizes, int n_in,
                              void* d_out, int out_size)
{
    const float* x  = (const float*)d_in[0];
    const float* Wq = (const float*)d_in[1];
    const float* bq = (const float*)d_in[2];
    const float* Wk = (const float*)d_in[3];
    const float* bk = (const float*)d_in[4];
    const float* Wv = (const float*)d_in[5];
    const float* bv = (const float*)d_in[6];
    const float* Wo = (const float*)d_in[7];
    const float* bo = (const float*)d_in[8];
    float* out = (float*)d_out;

    void *qp = nullptr, *kp = nullptr, *vp = nullptr, *ap = nullptr;
    cudaGetSymbolAddress(&qp, g_q);
    cudaGetSymbolAddress(&kp, g_k);
    cudaGetSymbolAddress(&vp, g_v);
    cudaGetSymbolAddress(&ap, g_attn);

    cudaFuncSetAttribute(attn_topk_kernel,
                         cudaFuncAttributeMaxDynamicSharedMemorySize, ATTN_SMEM);

    dim3 gg(D_ / GBN, M_ / GBM);   // (16, 32)
    sgemm_bias_kernel<<<gg, 256>>>(x, Wq, bq, (float*)qp);
    sgemm_bias_kernel<<<gg, 256>>>(x, Wk, bk, (float*)kp);
    sgemm_bias_kernel<<<gg, 256>>>(x, Wv, bv, (float*)vp);

    attn_topk_kernel<<<dim3(L_ / ITILE, H_, B_), 256, ATTN_SMEM>>>(
        (const float*)qp, (const float*)kp, (const float*)vp, (float*)ap);

    sgemm_bias_kernel<<<gg, 256>>>((const float*)ap, Wo, bo, out);
}

// round 3
// speedup vs baseline: 1.0024x; 1.0024x over previous
#include <cuda_runtime.h>
#include <math.h>
#include <stdint.h>

#define B_  4
#define L_  1024
#define D_  1024
#define H_  16
#define DH_ 64
#define M_  (B_*L_)   /* 4096 rows */

// Scratch (allocation-free rule: __device__ globals)
__device__ float g_q[(size_t)M_ * D_];
__device__ float g_k[(size_t)M_ * D_];
__device__ float g_v[(size_t)M_ * D_];
__device__ float g_attn[(size_t)M_ * D_];

// ---------------------------------------------------------------------------
// SGEMM + bias: C[M_,1024] = A[M_,1024] @ W[1024,1024] + bias[1024]
// 128x64 CTA tile, K-step 16, 256 threads, 8x4 per-thread microtile.
// ---------------------------------------------------------------------------
#define GBM 128
#define GBN 64
#define GBK 16

__global__ __launch_bounds__(256) void sgemm_bias_kernel(
    const float* __restrict__ A, const float* __restrict__ W,
    const float* __restrict__ bias, float* __restrict__ C)
{
    const int N = D_, K = D_;
    __shared__ float As[GBK][GBM + 4];   // stored transposed: As[k][m]
    __shared__ float Bs[GBK][GBN + 4];

    const int m0 = blockIdx.y * GBM;
    const int n0 = blockIdx.x * GBN;
    const int tid = threadIdx.x;
    const int tx = tid & 15;       // -> n
    const int ty = tid >> 4;       // -> m

    float acc[8][4];
#pragma unroll
    for (int i = 0; i < 8; i++)
#pragma unroll
        for (int j = 0; j < 4; j++) acc[i][j] = 0.f;

    for (int k0 = 0; k0 < K; k0 += GBK) {
        // Load A tile: 128x16 floats, 2 float4 per thread, store transposed
#pragma unroll
        for (int f = 0; f < 2; f++) {
            int t4  = tid + f * 256;          // 0..511 float4 index
            int row = t4 >> 2;                // 0..127
            int kk  = (t4 & 3) << 2;          // 0,4,8,12
            float4 v = *(const float4*)(A + (size_t)(m0 + row) * K + k0 + kk);
            As[kk + 0][row] = v.x;
            As[kk + 1][row] = v.y;
            As[kk + 2][row] = v.z;
            As[kk + 3][row] = v.w;
        }
        // Load W tile: 16x64 floats, 1 float4 per thread
        {
            int row = tid >> 4;               // 0..15
            int col = (tid & 15) << 2;        // 0..60
            *(float4*)&Bs[row][col] =
                *(const float4*)(W + (size_t)(k0 + row) * N + n0 + col);
        }
        __syncthreads();

#pragma unroll
        for (int k = 0; k < GBK; k++) {
            float a[8], b[4];
            float4 a0 = *(float4*)&As[k][ty * 8];
            float4 a1 = *(float4*)&As[k][ty * 8 + 4];
            a[0] = a0.x; a[1] = a0.y; a[2] = a0.z; a[3] = a0.w;
            a[4] = a1.x; a[5] = a1.y; a[6] = a1.z; a[7] = a1.w;
            float4 bv = *(float4*)&Bs[k][tx * 4];
            b[0] = bv.x; b[1] = bv.y; b[2] = bv.z; b[3] = bv.w;
#pragma unroll
            for (int i = 0; i < 8; i++)
#pragma unroll
                for (int j = 0; j < 4; j++)
                    acc[i][j] = fmaf(a[i], b[j], acc[i][j]);
        }
        __syncthreads();
    }

#pragma unroll
    for (int i = 0; i < 8; i++) {
        int m = m0 + ty * 8 + i;
#pragma unroll
        for (int j = 0; j < 4; j++) {
            int n = n0 + tx * 4 + j;
            C[(size_t)m * N + n] = acc[i][j] + bias[n];
        }
    }
}

// ---------------------------------------------------------------------------
// Attention: per CTA = (b, h, 32-row i-tile).
//   scores S[32][1024] in smem, softmax-max/Z, top-32 extraction per row,
//   renormalized weights, 32-term weighted V gather.
// ---------------------------------------------------------------------------
#define ITILE 32
#define ATTN_SMEM ((32 * 1024 + 32 * 64 + 64 * 65) * 4)   /* 155,904 B */

__global__ __launch_bounds__(256) void attn_topk_kernel(
    const float* __restrict__ Q, const float* __restrict__ K,
    const float* __restrict__ V, float* __restrict__ Oa)
{
    extern __shared__ float sm[];
    float* sS = sm;                      // 32*1024
    float* sQ = sS + 32 * 1024;          // 32*64
    float* sK = sQ + 32 * 64;            // 64 rows, stride 65 (bank-conflict free)

    const int itile = blockIdx.x;
    const int h     = blockIdx.y;
    const int b     = blockIdx.z;
    const int i0    = itile * ITILE;
    const int tid   = threadIdx.x;
    const int lane  = tid & 31;
    const int w     = tid >> 5;          // warp id 0..7
    const size_t headoff = (size_t)h * DH_;

    // Load Q tile (32x64)
#pragma unroll
    for (int f = 0; f < 2; f++) {
        int e4  = tid + f * 256;         // 0..511
        int row = e4 >> 4;               // 0..31
        int c4  = (e4 & 15) << 2;        // 0..60
        *(float4*)&sQ[row * 64 + c4] =
            *(const float4*)(Q + ((size_t)(b * L_ + i0 + row)) * D_ + headoff + c4);
    }
    __syncthreads();

    // Scores: S = (Q Kt)/8 over 16 chunks of 64 keys
    for (int jc = 0; jc < 16; jc++) {
        int j0 = jc * 64;
#pragma unroll
        for (int f = 0; f < 4; f++) {
            int e4  = tid + f * 256;     // 0..1023
            int row = e4 >> 4;           // 0..63
            int c4  = (e4 & 15) << 2;
            float4 v = *(const float4*)(K + ((size_t)(b * L_ + j0 + row)) * D_ + headoff + c4);
            float* dst = &sK[row * 65 + c4];
            dst[0] = v.x; dst[1] = v.y; dst[2] = v.z; dst[3] = v.w;
        }
        __syncthreads();

        float acc[4][2];
#pragma unroll
        for (int r = 0; r < 4; r++) { acc[r][0] = 0.f; acc[r][1] = 0.f; }
#pragma unroll 4
        for (int k = 0; k < 64; k++) {
            float kv0 = sK[lane * 65 + k];
            float kv1 = sK[(lane + 32) * 65 + k];
#pragma unroll
            for (int r = 0; r < 4; r++) {
                float qv = sQ[(w + 8 * r) * 64 + k];
                acc[r][0] = fmaf(qv, kv0, acc[r][0]);
                acc[r][1] = fmaf(qv, kv1, acc[r][1]);
            }
        }
#pragma unroll
        for (int r = 0; r < 4; r++) {
            sS[(w + 8 * r) * 1024 + j0 + lane]      = acc[r][0] * 0.125f;
            sS[(w + 8 * r) * 1024 + j0 + lane + 32] = acc[r][1] * 0.125f;
        }
        __syncthreads();
    }

    // Per-warp rows {w, w+8, w+16, w+24}: softmax stats, top-32, output
    for (int rr = 0; rr < 4; rr++) {
        int i = w + rr * 8;
        float* row = sS + i * 1024;

        float m = -1e30f;
#pragma unroll
        for (int t = 0; t < 32; t++) m = fmaxf(m, row[lane + 32 * t]);
#pragma unroll
        for (int o = 16; o; o >>= 1) m = fmaxf(m, __shfl_xor_sync(0xffffffffu, m, o));

        float z = 0.f;
#pragma unroll
        for (int t = 0; t < 32; t++) {
            float e = __expf(row[lane + 32 * t] - m);
            row[lane + 32 * t] = e;
            z += e;
        }
#pragma unroll
        for (int o = 16; o; o >>= 1) z += __shfl_xor_sync(0xffffffffu, z, o);

        // lane-local best over its 32-element stripe (j % 32 == lane)
        float bv = -1.f; int bj = 0;
#pragma unroll
        for (int t = 0; t < 32; t++) {
            float vv = row[lane + 32 * t];
            if (vv > bv) { bv = vv; bj = lane + 32 * t; }
        }

        float sumk = 0.f, selw = 0.f; int selj = 0;
        for (int s = 0; s < 32; s++) {
            float v = bv; int j = bj;
#pragma unroll
            for (int o = 16; o; o >>= 1) {
                float v2 = __shfl_xor_sync(0xffffffffu, v, o);
                int   j2 = __shfl_xor_sync(0xffffffffu, j, o);
                if (v2 > v || (v2 == v && j2 < j)) { v = v2; j = j2; }
            }
            sumk += v;
            if (lane == s) { selw = v; selj = j; }
            if ((j & 31) == lane) {           // winning lane: consume + rescan
                row[j] = -1.f;
                bv = -1.f; bj = 0;
#pragma unroll
                for (int t = 0; t < 32; t++) {
                    float vv = row[lane + 32 * t];
                    if (vv > bv) { bv = vv; bj = lane + 32 * t; }
                }
            }
        }

        // w_j = e_j / (sum_top32(e) + 1e-8 * Z_e)  — exact renormalization
        float wgt = selw / (sumk + 1e-8f * z);

        float acc0 = 0.f, acc1 = 0.f;
#pragma unroll
        for (int t = 0; t < 32; t++) {
            int   j  = __shfl_sync(0xffffffffu, selj, t);
            float ww = __shfl_sync(0xffffffffu, wgt,  t);
            const float* vr = V + ((size_t)(b * L_ + j)) * D_ + headoff;
            acc0 = fmaf(ww, vr[lane], acc0);
            acc1 = fmaf(ww, vr[lane + 32], acc1);
        }
        size_t orow = ((size_t)(b * L_ + i0 + i)) * D_ + headoff;
        Oa[orow + lane]      = acc0;
        Oa[orow + lane + 32] = acc1;
    }
}

// ---------------------------------------------------------------------------
extern "C" void kernel_launch(void* const* d_in, const int* in_sizes, int n_in,
                              void* d_out, int out_size)
{
    const float* x  = (const float*)d_in[0];
    const float* Wq = (const float*)d_in[1];
    const float* bq = (const float*)d_in[2];
    const float* Wk = (const float*)d_in[3];
    const float* bk = (const float*)d_in[4];
    const float* Wv = (const float*)d_in[5];
    const float* bv = (const float*)d_in[6];
    const float* Wo = (const float*)d_in[7];
    const float* bo = (const float*)d_in[8];
    float* out = (float*)d_out;

    void *qp = nullptr, *kp = nullptr, *vp = nullptr, *ap = nullptr;
    cudaGetSymbolAddress(&qp, g_q);
    cudaGetSymbolAddress(&kp, g_k);
    cudaGetSymbolAddress(&vp, g_v);
    cudaGetSymbolAddress(&ap, g_attn);

    cudaFuncSetAttribute(attn_topk_kernel,
                         cudaFuncAttributeMaxDynamicSharedMemorySize, ATTN_SMEM);

    dim3 gg(D_ / GBN, M_ / GBM);   // (16, 32)
    sgemm_bias_kernel<<<gg, 256>>>(x, Wq, bq, (float*)qp);
    sgemm_bias_kernel<<<gg, 256>>>(x, Wk, bk, (float*)kp);
    sgemm_bias_kernel<<<gg, 256>>>(x, Wv, bv, (float*)vp);

    attn_topk_kernel<<<dim3(L_ / ITILE, H_, B_), 256, ATTN_SMEM>>>(
        (const float*)qp, (const float*)kp, (const float*)vp, (float*)ap);

    sgemm_bias_kernel<<<gg, 256>>>((const float*)ap, Wo, bo, out);
}